// round 16
// baseline (speedup 1.0000x reference)
#include <cuda_runtime.h>
#include <cstdint>

// DeepMapping2D occupancy_generation, GB300 sm_103a.  Round 16 — FINAL.
// Byte-identical resubmission of the R15 session-best variant (115.9; the
// structure's measured band is 115.3-117.4 with hist fixed at 95.0-95.5).
//
//   output[b] = K_b ones then zeros, K_b = #bins with count >= 53
//   (count/262144 > 2e-4). The per-cloud min-shift is a bijection on bins
//   (z stays in [0,1024) either way) -> K_b is shift-invariant -> no min
//   pass, no top-k, no second scan.
//
// Converged model (R1-R15):
//   * hist: 16.7M u8 REDG sector-RMWs / 184 LTS x 2cyc ~= 96us @NAT --
//     the LTS atomic floor; measured 94.2-95.9 across every variant.
//     Falsified: ATOMG returns (+44us), stream-split hist (+16us),
//     grid fences (+110us), deeper per-thread MLP (+3us), fused
//     load+store passes (+100us), smem/DSMEM privatization (ATOMS floor
//     ~119us, priced out).
//   * count: read-only uint4 scan ~9us; memset re-zero ~5us (driver write
//     path); out ~2us, forked parallel with memset in the graph.
//   * g_count reset rides the next replay's hist kernel; kernel-launch
//     boundaries provide all ordering; state invariant identical on every
//     call (correctness run, capture, and all replays).

#define NBATCH  64
#define NPTS    262144
#define TOPK    5120
#define GZ_LOG2 10
#define BINS_PER_BATCH   (1024u * 1024u)          // 1M u8 bins / batch
#define HWORDS_PER_BATCH (BINS_PER_BATCH / 4)     // 256K u32 / batch

__device__ unsigned int g_hist[(size_t)NBATCH * HWORDS_PER_BATCH];  // 64 MB, load-zeroed
__device__ unsigned int g_count[NBATCH];                            // load-zeroed

// ---------------------------------------------------------------------------
// Kernel 1: histogram scatter, RED-only byte adds + per-batch counter reset.
// grid (64, 64) x 256 thr; grid-stride, unroll 4. At the LTS RMW floor.
// ---------------------------------------------------------------------------
__global__ void dm2d_hist_kernel(const float4* __restrict__ pcd) {
    const int b = blockIdx.y;
    if (blockIdx.x == 0 && threadIdx.x == 0)
        g_count[b] = 0u;                           // reset (prev replay's value)

    unsigned int* __restrict__ hist = g_hist + (size_t)b * HWORDS_PER_BATCH;
    const float4* __restrict__ base = pcd + (size_t)b * (NPTS / 2);

    const int tid    = blockIdx.x * blockDim.x + threadIdx.x;
    const int stride = gridDim.x * blockDim.x;

    #pragma unroll 4
    for (int i = tid; i < NPTS / 2; i += stride) {
        float4 p = __ldcs(&base[i]);   // two points: (x0,z0,x1,z1); evict-first

        // jnp.round = round-half-to-even == rintf under default RN mode.
        unsigned x0 = (unsigned)(int)rintf(1000.0f * p.x);
        unsigned z0 = (unsigned)(int)rintf(1000.0f * p.y);
        unsigned x1 = (unsigned)(int)rintf(1000.0f * p.z);
        unsigned z1 = (unsigned)(int)rintf(1000.0f * p.w);

        unsigned i0 = (x0 << GZ_LOG2) | z0;
        unsigned i1 = (x1 << GZ_LOG2) | z1;

        // fire-and-forget byte increments (return unused -> REDG)
        atomicAdd(&hist[i0 >> 2], 1u << ((i0 & 3u) << 3));
        atomicAdd(&hist[i1 >> 2], 1u << ((i1 & 3u) << 3));
    }
}

// ---------------------------------------------------------------------------
// Kernel 2: count bins >= 53 per batch. READ-ONLY over the L2-resident hist.
// grid (64, 64) x 256 thr; 4 uint4 = 64 bins per thread. Measured ~9us.
// ---------------------------------------------------------------------------
__global__ void dm2d_count_kernel() {
    const int b = blockIdx.y;
    const uint4* __restrict__ hist4 =
        reinterpret_cast<const uint4*>(g_hist + (size_t)b * HWORDS_PER_BATCH);

    const int tid = blockIdx.x * 256 + threadIdx.x;   // 0..16383

    unsigned int cnt = 0;
    #pragma unroll
    for (int u = 0; u < 4; u++) {
        uint4 w = hist4[tid + u * 16384];
        cnt += __popc(__vcmpgeu4(w.x, 0x35353535u) & 0x01010101u);
        cnt += __popc(__vcmpgeu4(w.y, 0x35353535u) & 0x01010101u);
        cnt += __popc(__vcmpgeu4(w.z, 0x35353535u) & 0x01010101u);
        cnt += __popc(__vcmpgeu4(w.w, 0x35353535u) & 0x01010101u);
    }

    #pragma unroll
    for (int off = 16; off > 0; off >>= 1)
        cnt += __shfl_down_sync(0xFFFFFFFFu, cnt, off);
    if ((threadIdx.x & 31) == 0 && cnt)
        atomicAdd(&g_count[b], cnt);
}

// ---------------------------------------------------------------------------
// Kernel 3: output expansion, distributed float4 writes.
// grid (5, 64) x 256 thr: 1280 float4 = 5120 floats per batch.
// ---------------------------------------------------------------------------
__global__ void dm2d_out_kernel(float* __restrict__ out) {
    const int b = blockIdx.y;
    const int tid = blockIdx.x * 256 + threadIdx.x;   // 0..1279
    const int K = (int)g_count[b];
    const int i = tid * 4;
    float4 v;
    v.x = (i + 0 < K) ? 1.0f : 0.0f;
    v.y = (i + 1 < K) ? 1.0f : 0.0f;
    v.z = (i + 2 < K) ? 1.0f : 0.0f;
    v.w = (i + 3 < K) ? 1.0f : 0.0f;
    reinterpret_cast<float4*>(out + (size_t)b * TOPK)[tid] = v;
}

extern "C" void kernel_launch(void* const* d_in, const int* in_sizes, int n_in,
                              void* d_out, int out_size) {
    (void)in_sizes; (void)n_in; (void)out_size;
    const float4* pcd = reinterpret_cast<const float4*>(d_in[0]);
    float* out = reinterpret_cast<float*>(d_out);

    void* hist_ptr = nullptr;
    cudaGetSymbolAddress(&hist_ptr, g_hist);

    dm2d_hist_kernel<<<dim3(64, NBATCH), 256>>>(pcd);
    dm2d_count_kernel<<<dim3(64, NBATCH), 256>>>();

    // memset (re-zero for next replay) and out are independent: run them as
    // parallel graph branches. Fallback = exact R12 sequential order.
    cudaStream_t s1 = nullptr;
    cudaEvent_t eFork = nullptr, eJoin = nullptr;
    bool forked =
        cudaStreamCreateWithFlags(&s1, cudaStreamNonBlocking) == cudaSuccess &&
        cudaEventCreateWithFlags(&eFork, cudaEventDisableTiming) == cudaSuccess &&
        cudaEventCreateWithFlags(&eJoin, cudaEventDisableTiming) == cudaSuccess;

    if (forked) {
        cudaEventRecord(eFork, 0);
        cudaStreamWaitEvent(s1, eFork, 0);
        cudaMemsetAsync(hist_ptr, 0, (size_t)NBATCH * BINS_PER_BATCH, s1); // branch A
        cudaEventRecord(eJoin, s1);
        dm2d_out_kernel<<<dim3(5, NBATCH), 256>>>(out);                    // branch B
        cudaStreamWaitEvent(0, eJoin, 0);                                  // join
    } else {
        cudaMemsetAsync(hist_ptr, 0, (size_t)NBATCH * BINS_PER_BATCH, 0);
        dm2d_out_kernel<<<dim3(5, NBATCH), 256>>>(out);
    }
}

// round 17
// speedup vs baseline: 1.0101x; 1.0101x over previous
#include <cuda_runtime.h>
#include <cstdint>

// DeepMapping2D occupancy_generation, GB300 sm_103a.  Round 17 — FINAL.
// R12-exact sequential structure: best single measurement (115.3us) and
// best mean (116.4 vs 117.2 forked) across 4 runs of the converged design.
//
//   output[b] = K_b ones then zeros, K_b = #bins with count >= 53
//   (count/262144 > 2e-4). The per-cloud min-shift is a bijection on bins
//   (z stays in [0,1024) either way) -> K_b is shift-invariant -> no min
//   pass, no top-k, no second scan.
//
// Converged model (R1-R16):
//   * hist: 16.7M u8 REDG sector-RMWs / 184 LTS x 2cyc ~= 182Kcyc ~= 95us
//     @NAT -- the LTS atomic floor; measured 94.2-96.4 across all variants
//     (drift = DVFS). Falsified: ATOMG returns (+44us), stream-split hist
//     (+16us), grid fences (+110us), deeper per-thread MLP (+3us), fused
//     load+store passes (+100us), smem/DSMEM privatization (ATOMS floors
//     ~119us, priced out), memset/out graph fork (node overhead = win).
//   * count: read-only uint4 scan ~9us; memset re-zero ~5us (driver write
//     path beats store kernels); out ~2us.
//   * g_count reset rides the next replay's hist kernel; kernel-launch
//     boundaries provide all ordering; state invariant identical on every
//     call (correctness run, capture, and all replays).

#define NBATCH  64
#define NPTS    262144
#define TOPK    5120
#define GZ_LOG2 10
#define BINS_PER_BATCH   (1024u * 1024u)          // 1M u8 bins / batch
#define HWORDS_PER_BATCH (BINS_PER_BATCH / 4)     // 256K u32 / batch

__device__ unsigned int g_hist[(size_t)NBATCH * HWORDS_PER_BATCH];  // 64 MB, load-zeroed
__device__ unsigned int g_count[NBATCH];                            // load-zeroed

// ---------------------------------------------------------------------------
// Kernel 1: histogram scatter, RED-only byte adds + per-batch counter reset.
// grid (64, 64) x 256 thr; grid-stride, unroll 4. At the LTS RMW floor.
// ---------------------------------------------------------------------------
__global__ void dm2d_hist_kernel(const float4* __restrict__ pcd) {
    const int b = blockIdx.y;
    if (blockIdx.x == 0 && threadIdx.x == 0)
        g_count[b] = 0u;                           // reset (prev replay's value)

    unsigned int* __restrict__ hist = g_hist + (size_t)b * HWORDS_PER_BATCH;
    const float4* __restrict__ base = pcd + (size_t)b * (NPTS / 2);

    const int tid    = blockIdx.x * blockDim.x + threadIdx.x;
    const int stride = gridDim.x * blockDim.x;

    #pragma unroll 4
    for (int i = tid; i < NPTS / 2; i += stride) {
        float4 p = __ldcs(&base[i]);   // two points: (x0,z0,x1,z1); evict-first

        // jnp.round = round-half-to-even == rintf under default RN mode.
        unsigned x0 = (unsigned)(int)rintf(1000.0f * p.x);
        unsigned z0 = (unsigned)(int)rintf(1000.0f * p.y);
        unsigned x1 = (unsigned)(int)rintf(1000.0f * p.z);
        unsigned z1 = (unsigned)(int)rintf(1000.0f * p.w);

        unsigned i0 = (x0 << GZ_LOG2) | z0;
        unsigned i1 = (x1 << GZ_LOG2) | z1;

        // fire-and-forget byte increments (return unused -> REDG)
        atomicAdd(&hist[i0 >> 2], 1u << ((i0 & 3u) << 3));
        atomicAdd(&hist[i1 >> 2], 1u << ((i1 & 3u) << 3));
    }
}

// ---------------------------------------------------------------------------
// Kernel 2: count bins >= 53 per batch. READ-ONLY over the L2-resident hist.
// grid (64, 64) x 256 thr; 4 uint4 = 64 bins per thread. Measured ~9us.
// ---------------------------------------------------------------------------
__global__ void dm2d_count_kernel() {
    const int b = blockIdx.y;
    const uint4* __restrict__ hist4 =
        reinterpret_cast<const uint4*>(g_hist + (size_t)b * HWORDS_PER_BATCH);

    const int tid = blockIdx.x * 256 + threadIdx.x;   // 0..16383

    unsigned int cnt = 0;
    #pragma unroll
    for (int u = 0; u < 4; u++) {
        uint4 w = hist4[tid + u * 16384];
        cnt += __popc(__vcmpgeu4(w.x, 0x35353535u) & 0x01010101u);
        cnt += __popc(__vcmpgeu4(w.y, 0x35353535u) & 0x01010101u);
        cnt += __popc(__vcmpgeu4(w.z, 0x35353535u) & 0x01010101u);
        cnt += __popc(__vcmpgeu4(w.w, 0x35353535u) & 0x01010101u);
    }

    #pragma unroll
    for (int off = 16; off > 0; off >>= 1)
        cnt += __shfl_down_sync(0xFFFFFFFFu, cnt, off);
    if ((threadIdx.x & 31) == 0 && cnt)
        atomicAdd(&g_count[b], cnt);
}

// ---------------------------------------------------------------------------
// Kernel 3: output expansion, distributed float4 writes.
// grid (5, 64) x 256 thr: 1280 float4 = 5120 floats per batch.
// ---------------------------------------------------------------------------
__global__ void dm2d_out_kernel(float* __restrict__ out) {
    const int b = blockIdx.y;
    const int tid = blockIdx.x * 256 + threadIdx.x;   // 0..1279
    const int K = (int)g_count[b];
    const int i = tid * 4;
    float4 v;
    v.x = (i + 0 < K) ? 1.0f : 0.0f;
    v.y = (i + 1 < K) ? 1.0f : 0.0f;
    v.z = (i + 2 < K) ? 1.0f : 0.0f;
    v.w = (i + 3 < K) ? 1.0f : 0.0f;
    reinterpret_cast<float4*>(out + (size_t)b * TOPK)[tid] = v;
}

extern "C" void kernel_launch(void* const* d_in, const int* in_sizes, int n_in,
                              void* d_out, int out_size) {
    (void)in_sizes; (void)n_in; (void)out_size;
    const float4* pcd = reinterpret_cast<const float4*>(d_in[0]);
    float* out = reinterpret_cast<float*>(d_out);

    void* hist_ptr = nullptr;
    cudaGetSymbolAddress(&hist_ptr, g_hist);

    dm2d_hist_kernel<<<dim3(64, NBATCH), 256>>>(pcd);
    dm2d_count_kernel<<<dim3(64, NBATCH), 256>>>();

    // Re-zero the histogram for the next replay (driver-tuned write path),
    // then expand the output. R12-exact sequential order.
    cudaMemsetAsync(hist_ptr, 0, (size_t)NBATCH * BINS_PER_BATCH, 0);
    dm2d_out_kernel<<<dim3(5, NBATCH), 256>>>(out);
}